// round 2
// baseline (speedup 1.0000x reference)
#include <cuda_runtime.h>
#include <cstdint>
#include <cstddef>

#define BB 4
#define NN 4096
#define MM 4096
#define CC 128
#define CAP 512

#define GG 10
#define NCELL (GG*GG)

#define THR2 0.04f
#define NEG_INV_SCALE (-99.9999000001f)   /* -(1/(0.01+1e-8)) */

// ---------------- scratch (device globals; no allocation) ----------------
__device__ int    g_mask_i32;

// cell-sorted valid points (loc + original index) and cell range starts
__device__ float2 g_ss_loc[BB*NN];
__device__ int    g_ss_idx[BB*NN];
__device__ int    g_s_cstart[BB][NCELL+1];
__device__ float2 g_ts_loc[BB*MM];
__device__ int    g_ts_idx[BB*MM];
__device__ int    g_t_cstart[BB][NCELL+1];

__device__ int2   g_rowlist[(size_t)BB*MM*CAP];   // {src idx n, logK bits}
__device__ int    g_rowcnt[BB*MM];
__device__ int2   g_collist[(size_t)BB*NN*CAP];   // {tgt idx m, logK bits}
__device__ int    g_colcnt[BB*NN];

__device__ float  g_u[BB*MM];
__device__ float  g_v[BB*NN];
__device__ int    g_count0[BB];                   // rows with u == +1e9 exactly

__device__ __forceinline__ bool mask_at(const void* p, int i) {
    return g_mask_i32 ? (((const int*)p)[i] != 0)
                      : (((const unsigned char*)p)[i] != 0);
}

__device__ __forceinline__ int cell_of(float2 p) {
    int cx = (int)(p.x * GG); cx = min(max(cx, 0), GG - 1);
    int cy = (int)(p.y * GG); cy = min(max(cy, 0), GG - 1);
    return cy * GG + cx;
}

// ---------------- 0: detect mask dtype (bool-u8 vs int32) ----------------
__global__ void k_detect(const unsigned char* __restrict__ sm) {
    __shared__ int flag;
    if (threadIdx.x == 0) flag = 0;
    __syncthreads();
    int acc = 0;
    for (int p = threadIdx.x; p < 16384; p += blockDim.x)
        if (p & 3) acc |= sm[p];
    if (acc) atomicOr(&flag, 1);
    __syncthreads();
    if (threadIdx.x == 0) g_mask_i32 = (flag == 0);
}

// ------- 1: deterministic stable counting sort into 10x10 cells ----------
// One warp per (side, batch): 8 warps total, one block.
__global__ void k_sort(const float* __restrict__ slocs,
                       const float* __restrict__ tlocs,
                       const void* __restrict__ smask,
                       const void* __restrict__ tmask) {
    __shared__ int soff[8][NCELL];
    int w = threadIdx.x >> 5, lane = threadIdx.x & 31;
    int which = w >> 2, b = w & 3;
    const void*   mk   = which ? tmask : smask;
    const float2* loc  = (const float2*)(which ? tlocs : slocs);
    float2*       oloc = which ? g_ts_loc : g_ss_loc;
    int*          oidx = which ? g_ts_idx : g_ss_idx;
    int base = b * NN;
    int* off = soff[w];
    for (int c = lane; c < NCELL; c += 32) off[c] = 0;
    __syncwarp();
    // pass 1: per-cell counts
    for (int i0 = 0; i0 < NN; i0 += 32) {
        int i = i0 + lane;
        if (mask_at(mk, base + i)) {
            atomicAdd(&off[cell_of(loc[base + i])], 1);
        }
    }
    __syncwarp();
    // exclusive scan (serial on lane 0: 100 entries)
    if (lane == 0) {
        int run = 0;
        int* cst = which ? g_t_cstart[b] : g_s_cstart[b];
        for (int c = 0; c < NCELL; c++) {
            int t = off[c]; off[c] = run; cst[c] = run; run += t;
        }
        cst[NCELL] = run;
    }
    __syncwarp();
    // pass 2: stable scatter (original index order within each cell)
    for (int i0 = 0; i0 < NN; i0 += 32) {
        int i = i0 + lane;
        bool m = mask_at(mk, base + i);
        float2 p = m ? loc[base + i] : make_float2(0.f, 0.f);
        int cell = m ? cell_of(p) : (1000 + lane);   // unique dummy for invalid
        unsigned peers = __match_any_sync(0xffffffffu, cell);
        if (m) {
            int leader = __ffs(peers) - 1;
            int rank = __popc(peers & ((1u << lane) - 1u));
            int bse = 0;
            if (lane == leader) bse = off[cell];
            bse = __shfl_sync(peers, bse, leader);
            int pos = base + bse + rank;
            oloc[pos] = p;
            oidx[pos] = i;
            if (lane == leader) off[cell] = bse + __popc(peers);
        }
    }
}

// ---------------- 2: build row adjacency (warp per target, binned) -------
__global__ void k_build_rows(const float* __restrict__ tlocs,
                             const void* __restrict__ tmask) {
    int gw = (blockIdx.x * blockDim.x + threadIdx.x) >> 5;
    int lane = threadIdx.x & 31;
    if (gw >= BB * MM) return;
    int b = gw >> 12, base = b * NN;
    if (!mask_at(tmask, gw)) { if (!lane) g_rowcnt[gw] = 0; return; }
    float2 t = ((const float2*)tlocs)[gw];
    int cx = min(max((int)(t.x * GG), 0), GG - 1);
    int cy = min(max((int)(t.y * GG), 0), GG - 1);
    int cx0 = max(cx - 2, 0), cx1 = min(cx + 2, GG - 1);
    int cy0 = max(cy - 2, 0), cy1 = min(cy + 2, GG - 1);
    int2* lst = g_rowlist + (size_t)gw * CAP;
    int cnt = 0;
    for (int yy = cy0; yy <= cy1; yy++) {
        int beg = g_s_cstart[b][yy * GG + cx0];
        int end = g_s_cstart[b][yy * GG + cx1 + 1];
        for (int j0 = beg; j0 < end; j0 += 32) {
            int j = j0 + lane;
            bool pr = j < end;
            float2 s = pr ? g_ss_loc[base + j] : make_float2(1e30f, 1e30f);
            float dx = t.x - s.x, dy = t.y - s.y;
            float d2 = __fadd_rn(__fmul_rn(dx, dx), __fmul_rn(dy, dy));
            bool val = pr && (d2 < THR2);
            unsigned bal = __ballot_sync(0xffffffffu, val);
            if (val) {
                int pos = cnt + __popc(bal & ((1u << lane) - 1u));
                if (pos < CAP)
                    lst[pos] = make_int2(g_ss_idx[base + j],
                                         __float_as_int(__fmul_rn(d2, NEG_INV_SCALE)));
            }
            cnt += __popc(bal);
        }
    }
    if (!lane) g_rowcnt[gw] = min(cnt, CAP);
}

// ---------------- 3: build col adjacency (warp per source, binned) -------
__global__ void k_build_cols(const float* __restrict__ slocs,
                             const void* __restrict__ smask) {
    int gw = (blockIdx.x * blockDim.x + threadIdx.x) >> 5;
    int lane = threadIdx.x & 31;
    if (gw >= BB * NN) return;
    int b = gw >> 12, base = b * MM;
    if (!mask_at(smask, gw)) { if (!lane) g_colcnt[gw] = 0; return; }
    float2 s = ((const float2*)slocs)[gw];
    int cx = min(max((int)(s.x * GG), 0), GG - 1);
    int cy = min(max((int)(s.y * GG), 0), GG - 1);
    int cx0 = max(cx - 2, 0), cx1 = min(cx + 2, GG - 1);
    int cy0 = max(cy - 2, 0), cy1 = min(cy + 2, GG - 1);
    int2* lst = g_collist + (size_t)gw * CAP;
    int cnt = 0;
    for (int yy = cy0; yy <= cy1; yy++) {
        int beg = g_t_cstart[b][yy * GG + cx0];
        int end = g_t_cstart[b][yy * GG + cx1 + 1];
        for (int j0 = beg; j0 < end; j0 += 32) {
            int j = j0 + lane;
            bool pr = j < end;
            float2 t = pr ? g_ts_loc[base + j] : make_float2(1e30f, 1e30f);
            float dx = t.x - s.x, dy = t.y - s.y;
            float d2 = __fadd_rn(__fmul_rn(dx, dx), __fmul_rn(dy, dy));
            bool val = pr && (d2 < THR2);
            unsigned bal = __ballot_sync(0xffffffffu, val);
            if (val) {
                int pos = cnt + __popc(bal & ((1u << lane) - 1u));
                if (pos < CAP)
                    lst[pos] = make_int2(g_ts_idx[base + j],
                                         __float_as_int(__fmul_rn(d2, NEG_INV_SCALE)));
            }
            cnt += __popc(bal);
        }
    }
    if (!lane) g_colcnt[gw] = min(cnt, CAP);
}

// ---------------- 4: count0 per batch + zero v ----------------------------
__global__ void k_prep() {
    __shared__ int red[256];
    int b = blockIdx.x;
    int c = 0;
    for (int m = threadIdx.x; m < MM; m += blockDim.x)
        c += (g_rowcnt[b * MM + m] > 0);
    red[threadIdx.x] = c;
    __syncthreads();
    for (int s = 128; s; s >>= 1) {
        if (threadIdx.x < s) red[threadIdx.x] += red[threadIdx.x + s];
        __syncthreads();
    }
    if (threadIdx.x == 0) g_count0[b] = MM - red[0];
    for (int n = threadIdx.x; n < NN; n += blockDim.x) g_v[b * NN + n] = 0.0f;
}

// ---------------- 5: u update (one warp per target row) -------------------
__global__ void k_u() {
    int gw = (blockIdx.x * blockDim.x + threadIdx.x) >> 5;
    int lane = threadIdx.x & 31;
    if (gw >= BB * MM) return;
    int b = gw >> 12;
    int cnt = g_rowcnt[gw];
    if (cnt == 0) { if (!lane) g_u[gw] = 1e9f; return; }
    const int2* lst = g_rowlist + (size_t)gw * CAP;
    const float* v = g_v + b * NN;
    float mx = __int_as_float(0xff800000);
    for (int e = lane; e < cnt; e += 32) {
        int2 p = lst[e];
        mx = fmaxf(mx, __int_as_float(p.y) + v[p.x]);
    }
    for (int o = 16; o; o >>= 1) mx = fmaxf(mx, __shfl_xor_sync(0xffffffffu, mx, o));
    float s = 0.f;
    for (int e = lane; e < cnt; e += 32) {
        int2 p = lst[e];
        s += __expf(__int_as_float(p.y) + v[p.x] - mx);
    }
    for (int o = 16; o; o >>= 1) s += __shfl_xor_sync(0xffffffffu, s, o);
    if (!lane) g_u[gw] = -(mx + __logf(s));
}

// ---------------- 6: v update (one warp per source col) -------------------
// Rows with u==+1e9 contribute exp(0) exactly (fp32: -1e9+1e9 = 0) to EVERY
// column; there are count0 of them.
__global__ void k_v(const void* __restrict__ smask) {
    int gw = (blockIdx.x * blockDim.x + threadIdx.x) >> 5;
    int lane = threadIdx.x & 31;
    if (gw >= BB * NN) return;
    int b = gw >> 12;
    if (!mask_at(smask, gw)) { if (!lane) g_v[gw] = 0.f; return; }
    int cnt = g_colcnt[gw];
    float c0 = (float)g_count0[b];
    if (cnt == 0) {
        if (!lane) g_v[gw] = (c0 > 0.f) ? -__logf(c0) : 1e9f;
        return;
    }
    const int2* lst = g_collist + (size_t)gw * CAP;
    const float* u = g_u + b * MM;
    float mx = __int_as_float(0xff800000);
    for (int e = lane; e < cnt; e += 32) {
        int2 p = lst[e];
        mx = fmaxf(mx, __int_as_float(p.y) + u[p.x]);
    }
    for (int o = 16; o; o >>= 1) mx = fmaxf(mx, __shfl_xor_sync(0xffffffffu, mx, o));
    if (c0 > 0.f) mx = fmaxf(mx, 0.0f);
    float s = 0.f;
    for (int e = lane; e < cnt; e += 32) {
        int2 p = lst[e];
        s += __expf(__int_as_float(p.y) + u[p.x] - mx);
    }
    for (int o = 16; o; o >>= 1) s += __shfl_xor_sync(0xffffffffu, s, o);
    if (!lane) {
        float st = s + ((c0 > 0.f) ? c0 * __expf(-mx) : 0.f);
        g_v[gw] = -(mx + __logf(st));
    }
}

// ---------------- 7a: zero the output --------------------------------------
__global__ void k_zero(float4* __restrict__ out) {
    int i = blockIdx.x * blockDim.x + threadIdx.x;
    out[i] = make_float4(0.f, 0.f, 0.f, 0.f);
}

// ---------------- 7b: attn weights + feature gather (cell-ordered) --------
__global__ void k_out(const float* __restrict__ feats, float* __restrict__ out) {
    __shared__ int   s_idx[8][CAP];
    __shared__ float s_w[8][CAP];
    int wid = threadIdx.x >> 5, lane = threadIdx.x & 31;
    int gwp = (blockIdx.x * blockDim.x + threadIdx.x) >> 5;
    if (gwp >= BB * MM) return;
    int b = gwp >> 12, pos = gwp & (MM - 1);
    if (pos >= g_t_cstart[b][NCELL]) return;          // only valid targets (sorted)
    int m = g_ts_idx[b * MM + pos];
    int gw = b * MM + m;
    int cnt = g_rowcnt[gw];
    if (cnt == 0) return;                             // out already zeroed
    const int2* lst = g_rowlist + (size_t)gw * CAP;
    const float* v = g_v + b * NN;
    float um = g_u[gw];
    for (int e = lane; e < cnt; e += 32) {
        int2 p = lst[e];
        s_idx[wid][e] = p.x;
        s_w[wid][e]   = __expf(__int_as_float(p.y) + um + v[p.x]);
    }
    __syncwarp();
    float4 acc = make_float4(0.f, 0.f, 0.f, 0.f);
    const float4* f4 = ((const float4*)feats) + (size_t)b * NN * (CC / 4);
    int e = 0;
    for (; e + 4 <= cnt; e += 4) {
        int   n0 = s_idx[wid][e],     n1 = s_idx[wid][e + 1];
        int   n2 = s_idx[wid][e + 2], n3 = s_idx[wid][e + 3];
        float w0 = s_w[wid][e],       w1 = s_w[wid][e + 1];
        float w2 = s_w[wid][e + 2],   w3 = s_w[wid][e + 3];
        float4 a0 = f4[(size_t)n0 * 32 + lane];
        float4 a1 = f4[(size_t)n1 * 32 + lane];
        float4 a2 = f4[(size_t)n2 * 32 + lane];
        float4 a3 = f4[(size_t)n3 * 32 + lane];
        acc.x = fmaf(w0, a0.x, acc.x); acc.y = fmaf(w0, a0.y, acc.y);
        acc.z = fmaf(w0, a0.z, acc.z); acc.w = fmaf(w0, a0.w, acc.w);
        acc.x = fmaf(w1, a1.x, acc.x); acc.y = fmaf(w1, a1.y, acc.y);
        acc.z = fmaf(w1, a1.z, acc.z); acc.w = fmaf(w1, a1.w, acc.w);
        acc.x = fmaf(w2, a2.x, acc.x); acc.y = fmaf(w2, a2.y, acc.y);
        acc.z = fmaf(w2, a2.z, acc.z); acc.w = fmaf(w2, a2.w, acc.w);
        acc.x = fmaf(w3, a3.x, acc.x); acc.y = fmaf(w3, a3.y, acc.y);
        acc.z = fmaf(w3, a3.z, acc.z); acc.w = fmaf(w3, a3.w, acc.w);
    }
    for (; e < cnt; e++) {
        int n = s_idx[wid][e];
        float w = s_w[wid][e];
        float4 a = f4[(size_t)n * 32 + lane];
        acc.x = fmaf(w, a.x, acc.x); acc.y = fmaf(w, a.y, acc.y);
        acc.z = fmaf(w, a.z, acc.z); acc.w = fmaf(w, a.w, acc.w);
    }
    ((float4*)out)[(size_t)gw * 32 + lane] = acc;
}

// ---------------- launch ----------------
extern "C" void kernel_launch(void* const* d_in, const int* in_sizes, int n_in,
                              void* d_out, int out_size) {
    const float* feats = (const float*)d_in[0];
    const float* slocs = (const float*)d_in[1];
    const float* tlocs = (const float*)d_in[2];
    const void*  smask = d_in[3];
    const void*  tmask = d_in[4];
    float* out = (float*)d_out;

    k_detect<<<1, 256>>>((const unsigned char*)smask);
    k_sort<<<1, 256>>>(slocs, tlocs, smask, tmask);
    k_build_rows<<<(BB * MM) / 8, 256>>>(tlocs, tmask);
    k_build_cols<<<(BB * NN) / 8, 256>>>(slocs, smask);
    k_prep<<<BB, 256>>>();
    for (int it = 0; it < 3; it++) {
        k_u<<<(BB * MM) / 8, 256>>>();
        k_v<<<(BB * NN) / 8, 256>>>(smask);
    }
    k_zero<<<(BB * MM * 32) / 256, 256>>>((float4*)out);
    k_out<<<(BB * MM) / 8, 256>>>(feats, out);
}

// round 3
// speedup vs baseline: 1.0433x; 1.0433x over previous
#include <cuda_runtime.h>
#include <cstdint>
#include <cstddef>

#define BB 4
#define NN 4096
#define MM 4096
#define CC 128
#define CAP 512

#define GG 10
#define NCELL (GG*GG)

#define TT 8          // targets per warp in dense output kernel
#define GWARP 8       // warp-groups per cell

#define THR2 0.04f
#define NEG_INV_SCALE (-99.9999000001f)   /* -(1/(0.01+1e-8)) */

// ---------------- scratch (device globals; no allocation) ----------------
__device__ int    g_mask_i32;

// cell-sorted valid points (loc + original index) and cell range starts
__device__ float2 g_ss_loc[BB*NN];
__device__ int    g_ss_idx[BB*NN];
__device__ int    g_s_cstart[BB][NCELL+1];
__device__ float2 g_ts_loc[BB*MM];
__device__ int    g_ts_idx[BB*MM];
__device__ int    g_t_cstart[BB][NCELL+1];

__device__ int2   g_rowlist[(size_t)BB*MM*CAP];   // {src idx n, logK bits}
__device__ int    g_rowcnt[BB*MM];
__device__ int2   g_collist[(size_t)BB*NN*CAP];   // {tgt idx m, logK bits}
__device__ int    g_colcnt[BB*NN];

__device__ float  g_u[BB*MM];
__device__ float  g_v[BB*NN];
__device__ float  g_vs[BB*NN];                    // v permuted to sorted source order
__device__ int    g_count0[BB];                   // rows with u == +1e9 exactly

__device__ __forceinline__ bool mask_at(const void* p, int i) {
    return g_mask_i32 ? (((const int*)p)[i] != 0)
                      : (((const unsigned char*)p)[i] != 0);
}

__device__ __forceinline__ int cell_of(float2 p) {
    int cx = (int)(p.x * GG); cx = min(max(cx, 0), GG - 1);
    int cy = (int)(p.y * GG); cy = min(max(cy, 0), GG - 1);
    return cy * GG + cx;
}

// ---------------- 0: detect mask dtype (bool-u8 vs int32) ----------------
__global__ void k_detect(const unsigned char* __restrict__ sm) {
    __shared__ int flag;
    if (threadIdx.x == 0) flag = 0;
    __syncthreads();
    int acc = 0;
    for (int p = threadIdx.x; p < 16384; p += blockDim.x)
        if (p & 3) acc |= sm[p];
    if (acc) atomicOr(&flag, 1);
    __syncthreads();
    if (threadIdx.x == 0) g_mask_i32 = (flag == 0);
}

// ------- 1: deterministic stable counting sort, parallel (8 blocks) ------
// Block = (side, batch). 8 warps, each owns a contiguous 512-point range.
// Stable global order: (cell asc, original index asc).
__global__ void k_sort(const float* __restrict__ slocs,
                       const float* __restrict__ tlocs,
                       const void* __restrict__ smask,
                       const void* __restrict__ tmask) {
    __shared__ int hist[8][NCELL];
    __shared__ int cstart_s[NCELL + 1];
    int blk = blockIdx.x;
    int which = blk >> 2, b = blk & 3;
    const void*   mk   = which ? tmask : smask;
    const float2* loc  = (const float2*)(which ? tlocs : slocs);
    float2*       oloc = which ? g_ts_loc : g_ss_loc;
    int*          oidx = which ? g_ts_idx : g_ss_idx;
    int*          cst  = which ? g_t_cstart[b] : g_s_cstart[b];
    int tid = threadIdx.x, w = tid >> 5, lane = tid & 31;
    int base = b * NN;

    for (int c = tid; c < 8 * NCELL; c += 256) ((int*)hist)[c] = 0;
    __syncthreads();

    int i0w = w * 512;
    for (int i0 = i0w; i0 < i0w + 512; i0 += 32) {
        int i = i0 + lane;
        if (mask_at(mk, base + i))
            atomicAdd(&hist[w][cell_of(loc[base + i])], 1);
    }
    __syncthreads();

    if (tid == 0) {
        int run = 0;
        for (int c = 0; c < NCELL; c++) {
            cstart_s[c] = run;
            int t = 0;
            for (int ww = 0; ww < 8; ww++) t += hist[ww][c];
            run += t;
        }
        cstart_s[NCELL] = run;
        for (int c = 0; c <= NCELL; c++) cst[c] = cstart_s[c];
    }
    __syncthreads();

    // off(w, c) = cstart[c] + sum_{w'<w} hist[w'][c]; store in place
    if (tid < NCELL) {
        int run = cstart_s[tid];
        for (int ww = 0; ww < 8; ww++) {
            int h = hist[ww][tid];
            hist[ww][tid] = run;
            run += h;
        }
    }
    __syncthreads();

    for (int i0 = i0w; i0 < i0w + 512; i0 += 32) {
        int i = i0 + lane;
        bool m = mask_at(mk, base + i);
        float2 p = m ? loc[base + i] : make_float2(0.f, 0.f);
        int cell = m ? cell_of(p) : (1000 + lane);
        unsigned peers = __match_any_sync(0xffffffffu, cell);
        if (m) {
            int leader = __ffs(peers) - 1;
            int rank = __popc(peers & ((1u << lane) - 1u));
            int bse = 0;
            if (lane == leader) bse = hist[w][cell];
            bse = __shfl_sync(peers, bse, leader);
            int pos = base + bse + rank;
            oloc[pos] = p;
            oidx[pos] = i;
            if (lane == leader) hist[w][cell] = bse + __popc(peers);
        }
    }
}

// ---------------- 2: build row adjacency (warp per target, binned) -------
__global__ void k_build_rows(const float* __restrict__ tlocs,
                             const void* __restrict__ tmask) {
    int gw = (blockIdx.x * blockDim.x + threadIdx.x) >> 5;
    int lane = threadIdx.x & 31;
    if (gw >= BB * MM) return;
    int b = gw >> 12, base = b * NN;
    if (!mask_at(tmask, gw)) { if (!lane) g_rowcnt[gw] = 0; return; }
    float2 t = ((const float2*)tlocs)[gw];
    int cx = min(max((int)(t.x * GG), 0), GG - 1);
    int cy = min(max((int)(t.y * GG), 0), GG - 1);
    int cx0 = max(cx - 2, 0), cx1 = min(cx + 2, GG - 1);
    int cy0 = max(cy - 2, 0), cy1 = min(cy + 2, GG - 1);
    int2* lst = g_rowlist + (size_t)gw * CAP;
    int cnt = 0;
    for (int yy = cy0; yy <= cy1; yy++) {
        int beg = g_s_cstart[b][yy * GG + cx0];
        int end = g_s_cstart[b][yy * GG + cx1 + 1];
        for (int j0 = beg; j0 < end; j0 += 32) {
            int j = j0 + lane;
            bool pr = j < end;
            float2 s = pr ? g_ss_loc[base + j] : make_float2(1e30f, 1e30f);
            float dx = t.x - s.x, dy = t.y - s.y;
            float d2 = __fadd_rn(__fmul_rn(dx, dx), __fmul_rn(dy, dy));
            bool val = pr && (d2 < THR2);
            unsigned bal = __ballot_sync(0xffffffffu, val);
            if (val) {
                int pos = cnt + __popc(bal & ((1u << lane) - 1u));
                if (pos < CAP)
                    lst[pos] = make_int2(g_ss_idx[base + j],
                                         __float_as_int(__fmul_rn(d2, NEG_INV_SCALE)));
            }
            cnt += __popc(bal);
        }
    }
    if (!lane) g_rowcnt[gw] = min(cnt, CAP);
}

// ---------------- 3: build col adjacency (warp per source, binned) -------
__global__ void k_build_cols(const float* __restrict__ slocs,
                             const void* __restrict__ smask) {
    int gw = (blockIdx.x * blockDim.x + threadIdx.x) >> 5;
    int lane = threadIdx.x & 31;
    if (gw >= BB * NN) return;
    int b = gw >> 12, base = b * MM;
    if (!mask_at(smask, gw)) { if (!lane) g_colcnt[gw] = 0; return; }
    float2 s = ((const float2*)slocs)[gw];
    int cx = min(max((int)(s.x * GG), 0), GG - 1);
    int cy = min(max((int)(s.y * GG), 0), GG - 1);
    int cx0 = max(cx - 2, 0), cx1 = min(cx + 2, GG - 1);
    int cy0 = max(cy - 2, 0), cy1 = min(cy + 2, GG - 1);
    int2* lst = g_collist + (size_t)gw * CAP;
    int cnt = 0;
    for (int yy = cy0; yy <= cy1; yy++) {
        int beg = g_t_cstart[b][yy * GG + cx0];
        int end = g_t_cstart[b][yy * GG + cx1 + 1];
        for (int j0 = beg; j0 < end; j0 += 32) {
            int j = j0 + lane;
            bool pr = j < end;
            float2 t = pr ? g_ts_loc[base + j] : make_float2(1e30f, 1e30f);
            float dx = t.x - s.x, dy = t.y - s.y;
            float d2 = __fadd_rn(__fmul_rn(dx, dx), __fmul_rn(dy, dy));
            bool val = pr && (d2 < THR2);
            unsigned bal = __ballot_sync(0xffffffffu, val);
            if (val) {
                int pos = cnt + __popc(bal & ((1u << lane) - 1u));
                if (pos < CAP)
                    lst[pos] = make_int2(g_ts_idx[base + j],
                                         __float_as_int(__fmul_rn(d2, NEG_INV_SCALE)));
            }
            cnt += __popc(bal);
        }
    }
    if (!lane) g_colcnt[gw] = min(cnt, CAP);
}

// ---------------- 4: count0 per batch + zero v ----------------------------
__global__ void k_prep() {
    __shared__ int red[256];
    int b = blockIdx.x;
    int c = 0;
    for (int m = threadIdx.x; m < MM; m += blockDim.x)
        c += (g_rowcnt[b * MM + m] > 0);
    red[threadIdx.x] = c;
    __syncthreads();
    for (int s = 128; s; s >>= 1) {
        if (threadIdx.x < s) red[threadIdx.x] += red[threadIdx.x + s];
        __syncthreads();
    }
    if (threadIdx.x == 0) g_count0[b] = MM - red[0];
    for (int n = threadIdx.x; n < NN; n += blockDim.x) g_v[b * NN + n] = 0.0f;
}

// ---------------- 5: u update (one warp per target row) -------------------
__global__ void k_u() {
    int gw = (blockIdx.x * blockDim.x + threadIdx.x) >> 5;
    int lane = threadIdx.x & 31;
    if (gw >= BB * MM) return;
    int b = gw >> 12;
    int cnt = g_rowcnt[gw];
    if (cnt == 0) { if (!lane) g_u[gw] = 1e9f; return; }
    const int2* lst = g_rowlist + (size_t)gw * CAP;
    const float* v = g_v + b * NN;
    float mx = __int_as_float(0xff800000);
    for (int e = lane; e < cnt; e += 32) {
        int2 p = lst[e];
        mx = fmaxf(mx, __int_as_float(p.y) + v[p.x]);
    }
    for (int o = 16; o; o >>= 1) mx = fmaxf(mx, __shfl_xor_sync(0xffffffffu, mx, o));
    float s = 0.f;
    for (int e = lane; e < cnt; e += 32) {
        int2 p = lst[e];
        s += __expf(__int_as_float(p.y) + v[p.x] - mx);
    }
    for (int o = 16; o; o >>= 1) s += __shfl_xor_sync(0xffffffffu, s, o);
    if (!lane) g_u[gw] = -(mx + __logf(s));
}

// ---------------- 6: v update (one warp per source col) -------------------
// Rows with u==+1e9 contribute exp(0) exactly (fp32: -1e9+1e9 = 0) to EVERY
// column; there are count0 of them.
__global__ void k_v(const void* __restrict__ smask) {
    int gw = (blockIdx.x * blockDim.x + threadIdx.x) >> 5;
    int lane = threadIdx.x & 31;
    if (gw >= BB * NN) return;
    int b = gw >> 12;
    if (!mask_at(smask, gw)) { if (!lane) g_v[gw] = 0.f; return; }
    int cnt = g_colcnt[gw];
    float c0 = (float)g_count0[b];
    if (cnt == 0) {
        if (!lane) g_v[gw] = (c0 > 0.f) ? -__logf(c0) : 1e9f;
        return;
    }
    const int2* lst = g_collist + (size_t)gw * CAP;
    const float* u = g_u + b * MM;
    float mx = __int_as_float(0xff800000);
    for (int e = lane; e < cnt; e += 32) {
        int2 p = lst[e];
        mx = fmaxf(mx, __int_as_float(p.y) + u[p.x]);
    }
    for (int o = 16; o; o >>= 1) mx = fmaxf(mx, __shfl_xor_sync(0xffffffffu, mx, o));
    if (c0 > 0.f) mx = fmaxf(mx, 0.0f);
    float s = 0.f;
    for (int e = lane; e < cnt; e += 32) {
        int2 p = lst[e];
        s += __expf(__int_as_float(p.y) + u[p.x] - mx);
    }
    for (int o = 16; o; o >>= 1) s += __shfl_xor_sync(0xffffffffu, s, o);
    if (!lane) {
        float st = s + ((c0 > 0.f) ? c0 * __expf(-mx) : 0.f);
        g_v[gw] = -(mx + __logf(st));
    }
}

// ---------------- 6b: permute v into sorted source order -----------------
__global__ void k_perm_v() {
    int i = blockIdx.x * blockDim.x + threadIdx.x;
    if (i >= BB * NN) return;
    int b = i >> 12, pos = i & (NN - 1);
    if (pos < g_s_cstart[b][NCELL])
        g_vs[i] = g_v[b * NN + g_ss_idx[i]];
}

// ---------------- 7a: zero the output --------------------------------------
__global__ void k_zero(float4* __restrict__ out) {
    int i = blockIdx.x * blockDim.x + threadIdx.x;
    out[i] = make_float4(0.f, 0.f, 0.f, 0.f);
}

// ------- 7b: dense per-cell output: warp handles TT targets of one cell ---
// Streams the 5x5-cell candidate strips once; every surviving 512B feature
// row feeds up to TT targets. d2 recomputed with the exact rounding used by
// the builds, so validity is bitwise-consistent with the u/v solves.
__global__ void __launch_bounds__(32) k_out_dense(const float* __restrict__ feats,
                                                  float* __restrict__ out) {
    int blk = blockIdx.x;
    int g = blk & (GWARP - 1);
    int cellb = blk / GWARP;
    int cell = cellb % NCELL;
    int b = cellb / NCELL;
    int lane = threadIdx.x;

    int t_lo = g_t_cstart[b][cell], t_hi = g_t_cstart[b][cell + 1];
    if (t_lo + g * TT >= t_hi) return;

    int cx = cell % GG, cy = cell / GG;
    int cx0 = max(cx - 2, 0), cx1 = min(cx + 2, GG - 1);
    int cy0 = max(cy - 2, 0), cy1 = min(cy + 2, GG - 1);
    int tbase = b * MM, sbase = b * NN;
    const float4* f4 = (const float4*)feats + (size_t)b * NN * (CC / 4);

    for (int t0 = t_lo + g * TT; t0 < t_hi; t0 += GWARP * TT) {
        int nT = min(TT, t_hi - t0);
        float tx[TT], ty[TT], tu[TT];
        float4 acc[TT];
        int tidx[TT];
#pragma unroll
        for (int t = 0; t < TT; t++) {
            if (t < nT) {
                float2 tl = g_ts_loc[tbase + t0 + t];
                tidx[t] = g_ts_idx[tbase + t0 + t];
                tx[t] = tl.x; ty[t] = tl.y;
                tu[t] = g_u[tbase + tidx[t]];
            } else {
                tx[t] = 1e30f; ty[t] = 1e30f; tu[t] = 0.f; tidx[t] = 0;
            }
            acc[t] = make_float4(0.f, 0.f, 0.f, 0.f);
        }

        for (int yy = cy0; yy <= cy1; yy++) {
            int beg = g_s_cstart[b][yy * GG + cx0];
            int end = g_s_cstart[b][yy * GG + cx1 + 1];
            for (int j0 = beg; j0 < end; j0 += 32) {
                int j = j0 + lane;
                bool pr = j < end;
                float2 sl = pr ? g_ss_loc[sbase + j] : make_float2(1e30f, 1e30f);
                float vv = pr ? g_vs[sbase + j] : 0.f;
                int fidx = pr ? g_ss_idx[sbase + j] : 0;
                float w[TT];
                bool any = false;
#pragma unroll
                for (int t = 0; t < TT; t++) {
                    float dx = tx[t] - sl.x, dy = ty[t] - sl.y;
                    float d2 = __fadd_rn(__fmul_rn(dx, dx), __fmul_rn(dy, dy));
                    bool val = d2 < THR2;
                    float lw = __fmul_rn(d2, NEG_INV_SCALE) + tu[t] + vv;
                    w[t] = val ? __expf(lw) : 0.f;
                    any |= val;
                }
                unsigned bal = __ballot_sync(0xffffffffu, any);
                while (bal) {
                    int j2 = __ffs(bal) - 1;
                    bal &= bal - 1;
                    int fj = __shfl_sync(0xffffffffu, fidx, j2);
                    float4 a = f4[(size_t)fj * (CC / 4) + lane];
#pragma unroll
                    for (int t = 0; t < TT; t++) {
                        float wt = __shfl_sync(0xffffffffu, w[t], j2);
                        acc[t].x = fmaf(wt, a.x, acc[t].x);
                        acc[t].y = fmaf(wt, a.y, acc[t].y);
                        acc[t].z = fmaf(wt, a.z, acc[t].z);
                        acc[t].w = fmaf(wt, a.w, acc[t].w);
                    }
                }
            }
        }
#pragma unroll
        for (int t = 0; t < TT; t++) {
            if (t < nT)
                ((float4*)out)[((size_t)tbase + tidx[t]) * (CC / 4) + lane] = acc[t];
        }
    }
}

// ---------------- launch ----------------
extern "C" void kernel_launch(void* const* d_in, const int* in_sizes, int n_in,
                              void* d_out, int out_size) {
    const float* feats = (const float*)d_in[0];
    const float* slocs = (const float*)d_in[1];
    const float* tlocs = (const float*)d_in[2];
    const void*  smask = d_in[3];
    const void*  tmask = d_in[4];
    float* out = (float*)d_out;

    k_detect<<<1, 256>>>((const unsigned char*)smask);
    k_sort<<<8, 256>>>(slocs, tlocs, smask, tmask);
    k_build_rows<<<(BB * MM) / 8, 256>>>(tlocs, tmask);
    k_build_cols<<<(BB * NN) / 8, 256>>>(slocs, smask);
    k_prep<<<BB, 256>>>();
    for (int it = 0; it < 3; it++) {
        k_u<<<(BB * MM) / 8, 256>>>();
        k_v<<<(BB * NN) / 8, 256>>>(smask);
    }
    k_perm_v<<<(BB * NN) / 256, 256>>>();
    k_zero<<<(BB * MM * (CC / 4)) / 256, 256>>>((float4*)out);
    k_out_dense<<<BB * NCELL * GWARP, 32>>>(feats, out);
}

// round 4
// speedup vs baseline: 1.7059x; 1.6351x over previous
#include <cuda_runtime.h>
#include <cstdint>
#include <cstddef>

#define BB 4
#define NN 4096
#define MM 4096
#define CC 128

#define GG 10
#define NCELL (GG*GG)

#define TT 8          // rows per warp-group
#define OW 4          // warps per block
#define CELLBLK 2     // blocks per cell

#define THR2 0.04f
#define NEG_INV_SCALE (-99.9999000001f)   /* -(1/(0.01+1e-8)) */

// ---------------- scratch (device globals; no allocation) ----------------
__device__ int    g_mask_i32;

__device__ float2 g_ss_loc[BB*NN];
__device__ int    g_ss_idx[BB*NN];
__device__ int    g_s_cstart[BB][NCELL+1];
__device__ float2 g_ts_loc[BB*MM];
__device__ int    g_ts_idx[BB*MM];
__device__ int    g_t_cstart[BB][NCELL+1];

__device__ float  g_us[BB*MM];   // u in sorted-target order
__device__ float  g_vs[BB*NN];   // v in sorted-source order
__device__ int    g_nz[BB];      // # target rows with >=1 valid pair

__device__ __forceinline__ bool mask_at(const void* p, int i) {
    return g_mask_i32 ? (((const int*)p)[i] != 0)
                      : (((const unsigned char*)p)[i] != 0);
}

__device__ __forceinline__ int cell_of(float2 p) {
    int cx = (int)(p.x * GG); cx = min(max(cx, 0), GG - 1);
    int cy = (int)(p.y * GG); cy = min(max(cy, 0), GG - 1);
    return cy * GG + cx;
}

// ---------------- 0: detect mask dtype + zero state ----------------------
__global__ void k_detect(const unsigned char* __restrict__ sm) {
    __shared__ int flag;
    if (threadIdx.x == 0) flag = 0;
    __syncthreads();
    int acc = 0;
    for (int p = threadIdx.x; p < 16384; p += blockDim.x)
        if (p & 3) acc |= sm[p];
    if (acc) atomicOr(&flag, 1);
    for (int i = threadIdx.x; i < BB * NN; i += blockDim.x) g_vs[i] = 0.f;
    if (threadIdx.x < BB) g_nz[threadIdx.x] = 0;
    __syncthreads();
    if (threadIdx.x == 0) g_mask_i32 = (flag == 0);
}

// ------- 1: deterministic stable counting sort, parallel (8 blocks) ------
__global__ void k_sort(const float* __restrict__ slocs,
                       const float* __restrict__ tlocs,
                       const void* __restrict__ smask,
                       const void* __restrict__ tmask) {
    __shared__ int hist[8][NCELL];
    __shared__ int cstart_s[NCELL + 1];
    int blk = blockIdx.x;
    int which = blk >> 2, b = blk & 3;
    const void*   mk   = which ? tmask : smask;
    const float2* loc  = (const float2*)(which ? tlocs : slocs);
    float2*       oloc = which ? g_ts_loc : g_ss_loc;
    int*          oidx = which ? g_ts_idx : g_ss_idx;
    int*          cst  = which ? g_t_cstart[b] : g_s_cstart[b];
    int tid = threadIdx.x, w = tid >> 5, lane = tid & 31;
    int base = b * NN;

    for (int c = tid; c < 8 * NCELL; c += 256) ((int*)hist)[c] = 0;
    __syncthreads();

    int i0w = w * 512;
    for (int i0 = i0w; i0 < i0w + 512; i0 += 32) {
        int i = i0 + lane;
        if (mask_at(mk, base + i))
            atomicAdd(&hist[w][cell_of(loc[base + i])], 1);
    }
    __syncthreads();

    if (tid == 0) {
        int run = 0;
        for (int c = 0; c < NCELL; c++) {
            cstart_s[c] = run;
            int t = 0;
            for (int ww = 0; ww < 8; ww++) t += hist[ww][c];
            run += t;
        }
        cstart_s[NCELL] = run;
        for (int c = 0; c <= NCELL; c++) cst[c] = cstart_s[c];
    }
    __syncthreads();

    if (tid < NCELL) {
        int run = cstart_s[tid];
        for (int ww = 0; ww < 8; ww++) {
            int h = hist[ww][tid];
            hist[ww][tid] = run;
            run += h;
        }
    }
    __syncthreads();

    for (int i0 = i0w; i0 < i0w + 512; i0 += 32) {
        int i = i0 + lane;
        bool m = mask_at(mk, base + i);
        float2 p = m ? loc[base + i] : make_float2(0.f, 0.f);
        int cell = m ? cell_of(p) : (1000 + lane);
        unsigned peers = __match_any_sync(0xffffffffu, cell);
        if (m) {
            int leader = __ffs(peers) - 1;
            int rank = __popc(peers & ((1u << lane) - 1u));
            int bse = 0;
            if (lane == leader) bse = hist[w][cell];
            bse = __shfl_sync(peers, bse, leader);
            int pos = base + bse + rank;
            oloc[pos] = p;
            oidx[pos] = i;
            if (lane == leader) hist[w][cell] = bse + __popc(peers);
        }
    }
}

// -------- 2: u update, dense per-cell (warp-group of TT targets) ---------
// Single-pass LSE (valid logK in (-4,0], u/v small => no overflow/underflow).
__global__ __launch_bounds__(128) void k_u(int it) {
    int blk = blockIdx.x;
    int sub  = blk % CELLBLK;
    int cell = (blk / CELLBLK) % NCELL;
    int b    = blk / (CELLBLK * NCELL);
    int wid = threadIdx.x >> 5, lane = threadIdx.x & 31;
    int slot = sub * OW + wid;
    int t_lo = g_t_cstart[b][cell], t_hi = g_t_cstart[b][cell + 1];
    int cx = cell % GG, cy = cell / GG;
    int cx0 = max(cx - 2, 0), cx1 = min(cx + 2, GG - 1);
    int cy0 = max(cy - 2, 0), cy1 = min(cy + 2, GG - 1);
    int tbase = b * MM, sbase = b * NN;

    for (int t0 = t_lo + slot * TT; t0 < t_hi; t0 += CELLBLK * OW * TT) {
        int nT = min(TT, t_hi - t0);
        float tx[TT], ty[TT], s[TT];
#pragma unroll
        for (int t = 0; t < TT; t++) {
            if (t < nT) { float2 tl = g_ts_loc[tbase + t0 + t]; tx[t] = tl.x; ty[t] = tl.y; }
            else        { tx[t] = -1e30f; ty[t] = -1e30f; }
            s[t] = 0.f;
        }
        for (int yy = cy0; yy <= cy1; yy++) {
            int beg = g_s_cstart[b][yy * GG + cx0];
            int end = g_s_cstart[b][yy * GG + cx1 + 1];
            for (int j0 = beg; j0 < end; j0 += 32) {
                int j = j0 + lane;
                bool pr = j < end;
                float2 sl = pr ? g_ss_loc[sbase + j] : make_float2(1e30f, 1e30f);
                float vv  = pr ? g_vs[sbase + j] : 0.f;
#pragma unroll
                for (int t = 0; t < TT; t++) {
                    float dx = tx[t] - sl.x, dy = ty[t] - sl.y;
                    float d2 = __fadd_rn(__fmul_rn(dx, dx), __fmul_rn(dy, dy));
                    if (d2 < THR2) s[t] += __expf(__fmul_rn(d2, NEG_INV_SCALE) + vv);
                }
            }
        }
        int nzc = 0;
#pragma unroll
        for (int t = 0; t < TT; t++) {
            float tot = s[t];
            for (int o = 16; o; o >>= 1) tot += __shfl_xor_sync(0xffffffffu, tot, o);
            if (lane == 0 && t < nT) {
                g_us[tbase + t0 + t] = (tot > 0.f) ? -__logf(tot) : 1e9f;
                nzc += (tot > 0.f);
            }
        }
        if (it == 0 && lane == 0 && nzc) atomicAdd(&g_nz[b], nzc);
    }
}

// -------- 3: v update, dense per-cell (warp-group of TT sources) ---------
// Degenerate rows (u==+1e9): each contributes exp(0)=1 to EVERY column;
// there are (MM - nz) of them.
__global__ __launch_bounds__(128) void k_v() {
    int blk = blockIdx.x;
    int sub  = blk % CELLBLK;
    int cell = (blk / CELLBLK) % NCELL;
    int b    = blk / (CELLBLK * NCELL);
    int wid = threadIdx.x >> 5, lane = threadIdx.x & 31;
    int slot = sub * OW + wid;
    int s_lo = g_s_cstart[b][cell], s_hi = g_s_cstart[b][cell + 1];
    int cx = cell % GG, cy = cell / GG;
    int cx0 = max(cx - 2, 0), cx1 = min(cx + 2, GG - 1);
    int cy0 = max(cy - 2, 0), cy1 = min(cy + 2, GG - 1);
    int tbase = b * MM, sbase = b * NN;
    float c0 = (float)(MM - g_nz[b]);

    for (int t0 = s_lo + slot * TT; t0 < s_hi; t0 += CELLBLK * OW * TT) {
        int nT = min(TT, s_hi - t0);
        float sx[TT], sy[TT], s[TT];
#pragma unroll
        for (int t = 0; t < TT; t++) {
            if (t < nT) { float2 sl = g_ss_loc[sbase + t0 + t]; sx[t] = sl.x; sy[t] = sl.y; }
            else        { sx[t] = -1e30f; sy[t] = -1e30f; }
            s[t] = 0.f;
        }
        for (int yy = cy0; yy <= cy1; yy++) {
            int beg = g_t_cstart[b][yy * GG + cx0];
            int end = g_t_cstart[b][yy * GG + cx1 + 1];
            for (int j0 = beg; j0 < end; j0 += 32) {
                int j = j0 + lane;
                bool pr = j < end;
                float2 tl = pr ? g_ts_loc[tbase + j] : make_float2(1e30f, 1e30f);
                float uu  = pr ? g_us[tbase + j] : 0.f;
#pragma unroll
                for (int t = 0; t < TT; t++) {
                    float dx = tl.x - sx[t], dy = tl.y - sy[t];
                    float d2 = __fadd_rn(__fmul_rn(dx, dx), __fmul_rn(dy, dy));
                    if (d2 < THR2) s[t] += __expf(__fmul_rn(d2, NEG_INV_SCALE) + uu);
                }
            }
        }
#pragma unroll
        for (int t = 0; t < TT; t++) {
            float tot = s[t];
            for (int o = 16; o; o >>= 1) tot += __shfl_xor_sync(0xffffffffu, tot, o);
            if (lane == 0 && t < nT) {
                float st = tot + c0;
                g_vs[sbase + t0 + t] = (st > 0.f) ? -__logf(st) : 1e9f;
            }
        }
    }
}

// ---------------- 4a: zero the output -------------------------------------
__global__ void k_zero(float4* __restrict__ out) {
    int i = blockIdx.x * blockDim.x + threadIdx.x;
    out[i] = make_float4(0.f, 0.f, 0.f, 0.f);
}

// ------ 4b: output: warp owns TT targets; smem-compacted survivors -------
__global__ __launch_bounds__(128) void k_out(const float* __restrict__ feats,
                                             float* __restrict__ out) {
    __shared__ int   s_fi[OW][32];
    __shared__ float s_w[OW][32][9];   // 8 weights, padded to 9 (no bank conflicts)
    int blk = blockIdx.x;
    int sub  = blk % CELLBLK;
    int cell = (blk / CELLBLK) % NCELL;
    int b    = blk / (CELLBLK * NCELL);
    int wid = threadIdx.x >> 5, lane = threadIdx.x & 31;
    int slot = sub * OW + wid;
    int t_lo = g_t_cstart[b][cell], t_hi = g_t_cstart[b][cell + 1];
    int cx = cell % GG, cy = cell / GG;
    int cx0 = max(cx - 2, 0), cx1 = min(cx + 2, GG - 1);
    int cy0 = max(cy - 2, 0), cy1 = min(cy + 2, GG - 1);
    int tbase = b * MM, sbase = b * NN;
    const float4* f4 = (const float4*)feats + (size_t)b * NN * (CC / 4);

    for (int t0 = t_lo + slot * TT; t0 < t_hi; t0 += CELLBLK * OW * TT) {
        int nT = min(TT, t_hi - t0);
        float tx[TT], ty[TT], tu[TT];
        int tidx[TT];
        float4 acc[TT];
#pragma unroll
        for (int t = 0; t < TT; t++) {
            if (t < nT) {
                float2 tl = g_ts_loc[tbase + t0 + t];
                tx[t] = tl.x; ty[t] = tl.y;
                tu[t] = g_us[tbase + t0 + t];
                tidx[t] = g_ts_idx[tbase + t0 + t];
            } else { tx[t] = -1e30f; ty[t] = -1e30f; tu[t] = 0.f; tidx[t] = 0; }
            acc[t] = make_float4(0.f, 0.f, 0.f, 0.f);
        }
        for (int yy = cy0; yy <= cy1; yy++) {
            int beg = g_s_cstart[b][yy * GG + cx0];
            int end = g_s_cstart[b][yy * GG + cx1 + 1];
            for (int j0 = beg; j0 < end; j0 += 32) {
                int j = j0 + lane;
                bool pr = j < end;
                float2 sl = pr ? g_ss_loc[sbase + j] : make_float2(1e30f, 1e30f);
                float vv  = pr ? g_vs[sbase + j] : 0.f;
                int fidx  = pr ? g_ss_idx[sbase + j] : 0;
                float wt[TT];
                bool anyv = false;
#pragma unroll
                for (int t = 0; t < TT; t++) {
                    float dx = tx[t] - sl.x, dy = ty[t] - sl.y;
                    float d2 = __fadd_rn(__fmul_rn(dx, dx), __fmul_rn(dy, dy));
                    bool val = d2 < THR2;
                    wt[t] = val ? __expf(__fmul_rn(d2, NEG_INV_SCALE) + tu[t] + vv) : 0.f;
                    anyv |= val;
                }
                unsigned bal = __ballot_sync(0xffffffffu, anyv);
                if (anyv) {
                    int pos = __popc(bal & ((1u << lane) - 1u));
                    s_fi[wid][pos] = fidx;
#pragma unroll
                    for (int t = 0; t < TT; t++) s_w[wid][pos][t] = wt[t];
                }
                __syncwarp();
                int ns = __popc(bal);
                int e = 0;
                for (; e + 4 <= ns; e += 4) {
                    int fj0 = s_fi[wid][e],     fj1 = s_fi[wid][e + 1];
                    int fj2 = s_fi[wid][e + 2], fj3 = s_fi[wid][e + 3];
                    float4 a0 = f4[(size_t)fj0 * (CC / 4) + lane];
                    float4 a1 = f4[(size_t)fj1 * (CC / 4) + lane];
                    float4 a2 = f4[(size_t)fj2 * (CC / 4) + lane];
                    float4 a3 = f4[(size_t)fj3 * (CC / 4) + lane];
#pragma unroll
                    for (int t = 0; t < TT; t++) {
                        float w0 = s_w[wid][e][t],     w1 = s_w[wid][e + 1][t];
                        float w2 = s_w[wid][e + 2][t], w3 = s_w[wid][e + 3][t];
                        acc[t].x = fmaf(w0, a0.x, acc[t].x); acc[t].y = fmaf(w0, a0.y, acc[t].y);
                        acc[t].z = fmaf(w0, a0.z, acc[t].z); acc[t].w = fmaf(w0, a0.w, acc[t].w);
                        acc[t].x = fmaf(w1, a1.x, acc[t].x); acc[t].y = fmaf(w1, a1.y, acc[t].y);
                        acc[t].z = fmaf(w1, a1.z, acc[t].z); acc[t].w = fmaf(w1, a1.w, acc[t].w);
                        acc[t].x = fmaf(w2, a2.x, acc[t].x); acc[t].y = fmaf(w2, a2.y, acc[t].y);
                        acc[t].z = fmaf(w2, a2.z, acc[t].z); acc[t].w = fmaf(w2, a2.w, acc[t].w);
                        acc[t].x = fmaf(w3, a3.x, acc[t].x); acc[t].y = fmaf(w3, a3.y, acc[t].y);
                        acc[t].z = fmaf(w3, a3.z, acc[t].z); acc[t].w = fmaf(w3, a3.w, acc[t].w);
                    }
                }
                for (; e < ns; e++) {
                    int fj = s_fi[wid][e];
                    float4 a = f4[(size_t)fj * (CC / 4) + lane];
#pragma unroll
                    for (int t = 0; t < TT; t++) {
                        float w = s_w[wid][e][t];
                        acc[t].x = fmaf(w, a.x, acc[t].x); acc[t].y = fmaf(w, a.y, acc[t].y);
                        acc[t].z = fmaf(w, a.z, acc[t].z); acc[t].w = fmaf(w, a.w, acc[t].w);
                    }
                }
                __syncwarp();
            }
        }
#pragma unroll
        for (int t = 0; t < TT; t++) {
            if (t < nT)
                ((float4*)out)[((size_t)tbase + tidx[t]) * (CC / 4) + lane] = acc[t];
        }
    }
}

// ---------------- launch ----------------
extern "C" void kernel_launch(void* const* d_in, const int* in_sizes, int n_in,
                              void* d_out, int out_size) {
    const float* feats = (const float*)d_in[0];
    const float* slocs = (const float*)d_in[1];
    const float* tlocs = (const float*)d_in[2];
    const void*  smask = d_in[3];
    const void*  tmask = d_in[4];
    float* out = (float*)d_out;

    int grid = BB * NCELL * CELLBLK;   // 800
    k_detect<<<1, 256>>>((const unsigned char*)smask);
    k_sort<<<8, 256>>>(slocs, tlocs, smask, tmask);
    for (int it = 0; it < 3; it++) {
        k_u<<<grid, 128>>>(it);
        k_v<<<grid, 128>>>();
    }
    k_zero<<<(BB * MM * (CC / 4)) / 256, 256>>>((float4*)out);
    k_out<<<grid, 128>>>(feats, out);
}

// round 5
// speedup vs baseline: 1.7895x; 1.0490x over previous
#include <cuda_runtime.h>
#include <cstdint>
#include <cstddef>

#define BB 4
#define NN 4096
#define MM 4096
#define CC 128

#define GG 10
#define NCELL (GG*GG)

#define TT 8          // rows per block (row-group)
#define OW 4          // warps per block (candidate split)
#define G  4          // row-groups per cell covered by grid (loop beyond)

#define THR2 0.04f
#define NEG_INV_SCALE (-99.9999000001f)   /* -(1/(0.01+1e-8)) */

// ---------------- scratch (device globals; no allocation) ----------------
__device__ int    g_mask_i32;

__device__ float2 g_ss_loc[BB*NN];
__device__ int    g_ss_idx[BB*NN];
__device__ int    g_s_cstart[BB][NCELL+1];
__device__ float2 g_ts_loc[BB*MM];
__device__ int    g_ts_idx[BB*MM];
__device__ int    g_t_cstart[BB][NCELL+1];

__device__ float  g_us[BB*MM];   // u in sorted-target order
__device__ float  g_vs[BB*NN];   // v in sorted-source order
__device__ int    g_nz[BB];      // # target rows with >=1 valid pair

__device__ __forceinline__ bool mask_at(const void* p, int i) {
    return g_mask_i32 ? (((const int*)p)[i] != 0)
                      : (((const unsigned char*)p)[i] != 0);
}

__device__ __forceinline__ int cell_of(float2 p) {
    int cx = (int)(p.x * GG); cx = min(max(cx, 0), GG - 1);
    int cy = (int)(p.y * GG); cy = min(max(cy, 0), GG - 1);
    return cy * GG + cx;
}

// ---------------- 0: detect mask dtype + zero state ----------------------
__global__ void k_detect(const unsigned char* __restrict__ sm) {
    __shared__ int flag;
    if (threadIdx.x == 0) flag = 0;
    __syncthreads();
    int acc = 0;
    for (int p = threadIdx.x; p < 16384; p += blockDim.x)
        if (p & 3) acc |= sm[p];
    if (acc) atomicOr(&flag, 1);
    for (int i = threadIdx.x; i < BB * NN; i += blockDim.x) g_vs[i] = 0.f;
    if (threadIdx.x < BB) g_nz[threadIdx.x] = 0;
    __syncthreads();
    if (threadIdx.x == 0) g_mask_i32 = (flag == 0);
}

// ------- 1: deterministic stable counting sort, parallel (8 blocks) ------
__global__ void k_sort(const float* __restrict__ slocs,
                       const float* __restrict__ tlocs,
                       const void* __restrict__ smask,
                       const void* __restrict__ tmask) {
    __shared__ int hist[8][NCELL];
    __shared__ int cstart_s[NCELL + 1];
    int blk = blockIdx.x;
    int which = blk >> 2, b = blk & 3;
    const void*   mk   = which ? tmask : smask;
    const float2* loc  = (const float2*)(which ? tlocs : slocs);
    float2*       oloc = which ? g_ts_loc : g_ss_loc;
    int*          oidx = which ? g_ts_idx : g_ss_idx;
    int*          cst  = which ? g_t_cstart[b] : g_s_cstart[b];
    int tid = threadIdx.x, w = tid >> 5, lane = tid & 31;
    int base = b * NN;

    for (int c = tid; c < 8 * NCELL; c += 256) ((int*)hist)[c] = 0;
    __syncthreads();

    int i0w = w * 512;
    for (int i0 = i0w; i0 < i0w + 512; i0 += 32) {
        int i = i0 + lane;
        if (mask_at(mk, base + i))
            atomicAdd(&hist[w][cell_of(loc[base + i])], 1);
    }
    __syncthreads();

    if (tid == 0) {
        int run = 0;
        for (int c = 0; c < NCELL; c++) {
            cstart_s[c] = run;
            int t = 0;
            for (int ww = 0; ww < 8; ww++) t += hist[ww][c];
            run += t;
        }
        cstart_s[NCELL] = run;
        for (int c = 0; c <= NCELL; c++) cst[c] = cstart_s[c];
    }
    __syncthreads();

    if (tid < NCELL) {
        int run = cstart_s[tid];
        for (int ww = 0; ww < 8; ww++) {
            int h = hist[ww][tid];
            hist[ww][tid] = run;
            run += h;
        }
    }
    __syncthreads();

    for (int i0 = i0w; i0 < i0w + 512; i0 += 32) {
        int i = i0 + lane;
        bool m = mask_at(mk, base + i);
        float2 p = m ? loc[base + i] : make_float2(0.f, 0.f);
        int cell = m ? cell_of(p) : (1000 + lane);
        unsigned peers = __match_any_sync(0xffffffffu, cell);
        if (m) {
            int leader = __ffs(peers) - 1;
            int rank = __popc(peers & ((1u << lane) - 1u));
            int bse = 0;
            if (lane == leader) bse = hist[w][cell];
            bse = __shfl_sync(peers, bse, leader);
            int pos = base + bse + rank;
            oloc[pos] = p;
            oidx[pos] = i;
            if (lane == leader) hist[w][cell] = bse + __popc(peers);
        }
    }
}

// -------- 2: u update. Block per row-group; 4 warps split candidates -----
__global__ __launch_bounds__(128) void k_u(int it) {
    __shared__ float red[OW][TT];
    int blk = blockIdx.x;
    int g    = blk % G;
    int cell = (blk / G) % NCELL;
    int b    = blk / (G * NCELL);
    int tid = threadIdx.x, wid = tid >> 5, lane = tid & 31;
    int t_lo = g_t_cstart[b][cell], t_hi = g_t_cstart[b][cell + 1];
    int cx = cell % GG, cy = cell / GG;
    int cx0 = max(cx - 2, 0), cx1 = min(cx + 2, GG - 1);
    int cy0 = max(cy - 2, 0), cy1 = min(cy + 2, GG - 1);
    int tbase = b * MM, sbase = b * NN;

    for (int t0 = t_lo + g * TT; t0 < t_hi; t0 += G * TT) {
        int nT = min(TT, t_hi - t0);
        float tx[TT], ty[TT], s[TT];
#pragma unroll
        for (int t = 0; t < TT; t++) {
            if (t < nT) { float2 tl = g_ts_loc[tbase + t0 + t]; tx[t] = tl.x; ty[t] = tl.y; }
            else        { tx[t] = -1e30f; ty[t] = -1e30f; }
            s[t] = 0.f;
        }
        for (int yy = cy0; yy <= cy1; yy++) {
            int beg = g_s_cstart[b][yy * GG + cx0];
            int end = g_s_cstart[b][yy * GG + cx1 + 1];
            for (int j0 = beg + wid * 32; j0 < end; j0 += OW * 32) {
                int j = j0 + lane;
                bool pr = j < end;
                float2 sl = pr ? g_ss_loc[sbase + j] : make_float2(1e30f, 1e30f);
                float vv  = pr ? g_vs[sbase + j] : 0.f;
#pragma unroll
                for (int t = 0; t < TT; t++) {
                    float dx = tx[t] - sl.x, dy = ty[t] - sl.y;
                    float d2 = __fadd_rn(__fmul_rn(dx, dx), __fmul_rn(dy, dy));
                    if (d2 < THR2) s[t] += __expf(__fmul_rn(d2, NEG_INV_SCALE) + vv);
                }
            }
        }
#pragma unroll
        for (int t = 0; t < TT; t++) {
            float tot = s[t];
            for (int o = 16; o; o >>= 1) tot += __shfl_xor_sync(0xffffffffu, tot, o);
            if (lane == 0) red[wid][t] = tot;
        }
        __syncthreads();
        if (tid < TT) {
            float tot = red[0][tid] + red[1][tid] + red[2][tid] + red[3][tid];
            if (tid < nT) {
                g_us[tbase + t0 + tid] = (tot > 0.f) ? -__logf(tot) : 1e9f;
                if (it == 0 && tot > 0.f) atomicAdd(&g_nz[b], 1);
            }
        }
        __syncthreads();
    }
}

// -------- 3: v update. Block per row-group; 4 warps split candidates -----
__global__ __launch_bounds__(128) void k_v() {
    __shared__ float red[OW][TT];
    int blk = blockIdx.x;
    int g    = blk % G;
    int cell = (blk / G) % NCELL;
    int b    = blk / (G * NCELL);
    int tid = threadIdx.x, wid = tid >> 5, lane = tid & 31;
    int s_lo = g_s_cstart[b][cell], s_hi = g_s_cstart[b][cell + 1];
    int cx = cell % GG, cy = cell / GG;
    int cx0 = max(cx - 2, 0), cx1 = min(cx + 2, GG - 1);
    int cy0 = max(cy - 2, 0), cy1 = min(cy + 2, GG - 1);
    int tbase = b * MM, sbase = b * NN;
    float c0 = (float)(MM - g_nz[b]);

    for (int t0 = s_lo + g * TT; t0 < s_hi; t0 += G * TT) {
        int nT = min(TT, s_hi - t0);
        float sx[TT], sy[TT], s[TT];
#pragma unroll
        for (int t = 0; t < TT; t++) {
            if (t < nT) { float2 sl = g_ss_loc[sbase + t0 + t]; sx[t] = sl.x; sy[t] = sl.y; }
            else        { sx[t] = -1e30f; sy[t] = -1e30f; }
            s[t] = 0.f;
        }
        for (int yy = cy0; yy <= cy1; yy++) {
            int beg = g_t_cstart[b][yy * GG + cx0];
            int end = g_t_cstart[b][yy * GG + cx1 + 1];
            for (int j0 = beg + wid * 32; j0 < end; j0 += OW * 32) {
                int j = j0 + lane;
                bool pr = j < end;
                float2 tl = pr ? g_ts_loc[tbase + j] : make_float2(1e30f, 1e30f);
                float uu  = pr ? g_us[tbase + j] : 0.f;
#pragma unroll
                for (int t = 0; t < TT; t++) {
                    float dx = tl.x - sx[t], dy = tl.y - sy[t];
                    float d2 = __fadd_rn(__fmul_rn(dx, dx), __fmul_rn(dy, dy));
                    if (d2 < THR2) s[t] += __expf(__fmul_rn(d2, NEG_INV_SCALE) + uu);
                }
            }
        }
#pragma unroll
        for (int t = 0; t < TT; t++) {
            float tot = s[t];
            for (int o = 16; o; o >>= 1) tot += __shfl_xor_sync(0xffffffffu, tot, o);
            if (lane == 0) red[wid][t] = tot;
        }
        __syncthreads();
        if (tid < TT) {
            float tot = red[0][tid] + red[1][tid] + red[2][tid] + red[3][tid];
            if (tid < nT) {
                float st = tot + c0;
                g_vs[sbase + t0 + tid] = (st > 0.f) ? -__logf(st) : 1e9f;
            }
        }
        __syncthreads();
    }
}

// ---------------- 4a: zero the output -------------------------------------
__global__ void k_zero(float4* __restrict__ out) {
    int i = blockIdx.x * blockDim.x + threadIdx.x;
    out[i] = make_float4(0.f, 0.f, 0.f, 0.f);
}

// ------ 4b: output. Block per row-group; 4 warps split candidates --------
__global__ __launch_bounds__(128) void k_out(const float* __restrict__ feats,
                                             float* __restrict__ out) {
    __shared__ int    s_fi[OW][32];
    __shared__ float  s_w[OW][32][9];        // 8 wts padded to 9
    __shared__ float4 red4[OW * TT * 32];    // 16KB partials
    int blk = blockIdx.x;
    int g    = blk % G;
    int cell = (blk / G) % NCELL;
    int b    = blk / (G * NCELL);
    int tid = threadIdx.x, wid = tid >> 5, lane = tid & 31;
    int t_lo = g_t_cstart[b][cell], t_hi = g_t_cstart[b][cell + 1];
    int cx = cell % GG, cy = cell / GG;
    int cx0 = max(cx - 2, 0), cx1 = min(cx + 2, GG - 1);
    int cy0 = max(cy - 2, 0), cy1 = min(cy + 2, GG - 1);
    int tbase = b * MM, sbase = b * NN;
    const float4* f4 = (const float4*)feats + (size_t)b * NN * (CC / 4);

    for (int t0 = t_lo + g * TT; t0 < t_hi; t0 += G * TT) {
        int nT = min(TT, t_hi - t0);
        float tx[TT], ty[TT], tu[TT];
        int tidx[TT];
        float4 acc[TT];
#pragma unroll
        for (int t = 0; t < TT; t++) {
            if (t < nT) {
                float2 tl = g_ts_loc[tbase + t0 + t];
                tx[t] = tl.x; ty[t] = tl.y;
                tu[t] = g_us[tbase + t0 + t];
                tidx[t] = g_ts_idx[tbase + t0 + t];
            } else { tx[t] = -1e30f; ty[t] = -1e30f; tu[t] = 0.f; tidx[t] = 0; }
            acc[t] = make_float4(0.f, 0.f, 0.f, 0.f);
        }
        for (int yy = cy0; yy <= cy1; yy++) {
            int beg = g_s_cstart[b][yy * GG + cx0];
            int end = g_s_cstart[b][yy * GG + cx1 + 1];
            for (int j0 = beg + wid * 32; j0 < end; j0 += OW * 32) {
                int j = j0 + lane;
                bool pr = j < end;
                float2 sl = pr ? g_ss_loc[sbase + j] : make_float2(1e30f, 1e30f);
                float vv  = pr ? g_vs[sbase + j] : 0.f;
                int fidx  = pr ? g_ss_idx[sbase + j] : 0;
                float wt[TT];
                bool anyv = false;
#pragma unroll
                for (int t = 0; t < TT; t++) {
                    float dx = tx[t] - sl.x, dy = ty[t] - sl.y;
                    float d2 = __fadd_rn(__fmul_rn(dx, dx), __fmul_rn(dy, dy));
                    bool val = d2 < THR2;
                    wt[t] = val ? __expf(__fmul_rn(d2, NEG_INV_SCALE) + tu[t] + vv) : 0.f;
                    anyv |= val;
                }
                unsigned bal = __ballot_sync(0xffffffffu, anyv);
                if (anyv) {
                    int pos = __popc(bal & ((1u << lane) - 1u));
                    s_fi[wid][pos] = fidx;
#pragma unroll
                    for (int t = 0; t < TT; t++) s_w[wid][pos][t] = wt[t];
                }
                __syncwarp();
                int ns = __popc(bal);
                int e = 0;
                for (; e + 4 <= ns; e += 4) {
                    int fj0 = s_fi[wid][e],     fj1 = s_fi[wid][e + 1];
                    int fj2 = s_fi[wid][e + 2], fj3 = s_fi[wid][e + 3];
                    float4 a0 = f4[(size_t)fj0 * (CC / 4) + lane];
                    float4 a1 = f4[(size_t)fj1 * (CC / 4) + lane];
                    float4 a2 = f4[(size_t)fj2 * (CC / 4) + lane];
                    float4 a3 = f4[(size_t)fj3 * (CC / 4) + lane];
#pragma unroll
                    for (int t = 0; t < TT; t++) {
                        float w0 = s_w[wid][e][t],     w1 = s_w[wid][e + 1][t];
                        float w2 = s_w[wid][e + 2][t], w3 = s_w[wid][e + 3][t];
                        acc[t].x = fmaf(w0, a0.x, acc[t].x); acc[t].y = fmaf(w0, a0.y, acc[t].y);
                        acc[t].z = fmaf(w0, a0.z, acc[t].z); acc[t].w = fmaf(w0, a0.w, acc[t].w);
                        acc[t].x = fmaf(w1, a1.x, acc[t].x); acc[t].y = fmaf(w1, a1.y, acc[t].y);
                        acc[t].z = fmaf(w1, a1.z, acc[t].z); acc[t].w = fmaf(w1, a1.w, acc[t].w);
                        acc[t].x = fmaf(w2, a2.x, acc[t].x); acc[t].y = fmaf(w2, a2.y, acc[t].y);
                        acc[t].z = fmaf(w2, a2.z, acc[t].z); acc[t].w = fmaf(w2, a2.w, acc[t].w);
                        acc[t].x = fmaf(w3, a3.x, acc[t].x); acc[t].y = fmaf(w3, a3.y, acc[t].y);
                        acc[t].z = fmaf(w3, a3.z, acc[t].z); acc[t].w = fmaf(w3, a3.w, acc[t].w);
                    }
                }
                for (; e < ns; e++) {
                    int fj = s_fi[wid][e];
                    float4 a = f4[(size_t)fj * (CC / 4) + lane];
#pragma unroll
                    for (int t = 0; t < TT; t++) {
                        float w = s_w[wid][e][t];
                        acc[t].x = fmaf(w, a.x, acc[t].x); acc[t].y = fmaf(w, a.y, acc[t].y);
                        acc[t].z = fmaf(w, a.z, acc[t].z); acc[t].w = fmaf(w, a.w, acc[t].w);
                    }
                }
                __syncwarp();
            }
        }
        // block reduce partials -> out
#pragma unroll
        for (int t = 0; t < TT; t++)
            red4[(wid * TT + t) * 32 + lane] = acc[t];
        __syncthreads();
        for (int t = wid; t < nT; t += OW) {
            float4 a0 = red4[(0 * TT + t) * 32 + lane];
            float4 a1 = red4[(1 * TT + t) * 32 + lane];
            float4 a2 = red4[(2 * TT + t) * 32 + lane];
            float4 a3 = red4[(3 * TT + t) * 32 + lane];
            float4 r;
            r.x = (a0.x + a1.x) + (a2.x + a3.x);
            r.y = (a0.y + a1.y) + (a2.y + a3.y);
            r.z = (a0.z + a1.z) + (a2.z + a3.z);
            r.w = (a0.w + a1.w) + (a2.w + a3.w);
            ((float4*)out)[((size_t)tbase + tidx[t]) * (CC / 4) + lane] = r;
        }
        __syncthreads();
    }
}

// ---------------- launch ----------------
extern "C" void kernel_launch(void* const* d_in, const int* in_sizes, int n_in,
                              void* d_out, int out_size) {
    const float* feats = (const float*)d_in[0];
    const float* slocs = (const float*)d_in[1];
    const float* tlocs = (const float*)d_in[2];
    const void*  smask = d_in[3];
    const void*  tmask = d_in[4];
    float* out = (float*)d_out;

    int grid = BB * NCELL * G;   // 1600
    k_detect<<<1, 256>>>((const unsigned char*)smask);
    k_sort<<<8, 256>>>(slocs, tlocs, smask, tmask);
    for (int it = 0; it < 3; it++) {
        k_u<<<grid, 128>>>(it);
        k_v<<<grid, 128>>>();
    }
    k_zero<<<(BB * MM * (CC / 4)) / 256, 256>>>((float4*)out);
    k_out<<<grid, 128>>>(feats, out);
}